// round 1
// baseline (speedup 1.0000x reference)
#include <cuda_runtime.h>
#include <cuda_bf16.h>
#include <math.h>

// Problem constants
#define MROWS 16384   // B*S
#define LATENT 512
#define EDIM 512
#define NE 8192

// GEMM tiling
#define BM 128
#define BN 128
#define BKK 16
#define NTHREADS 256

// ---------------- device scratch (static, allocation-free) ----------------
__device__ float g_embn[NE * EDIM];                 // normalized embedding (16 MB)
__device__ float g_M[NE * LATENT];                  // M = emb_n @ W_in     (16 MB)
__device__ float g_t[NE];                           // t = emb_n @ b_in
__device__ unsigned long long g_best[MROWS];        // packed (score,idx)
__device__ int g_idx[MROWS];

// ---------------- f32x2 helpers ----------------
__device__ __forceinline__ unsigned long long pk2(float lo, float hi) {
    unsigned long long r;
    asm("mov.b64 %0, {%1, %2};" : "=l"(r) : "f"(lo), "f"(hi));
    return r;
}
__device__ __forceinline__ void fma2(unsigned long long& d, unsigned long long a, unsigned long long b) {
    asm("fma.rn.f32x2 %0, %1, %2, %0;" : "+l"(d) : "l"(a), "l"(b));
}
__device__ __forceinline__ float lo32(unsigned long long v) { return __uint_as_float((unsigned)v); }
__device__ __forceinline__ float hi32(unsigned long long v) { return __uint_as_float((unsigned)(v >> 32)); }

// ordered-float encoding: monotone unsigned mapping of fp32
__device__ __forceinline__ unsigned float_ord(float f) {
    unsigned u = __float_as_uint(f);
    return (u & 0x80000000u) ? ~u : (u | 0x80000000u);
}

// ---------------- kernel 0: init argmax scratch ----------------
__global__ void init_best_kernel() {
    int i = blockIdx.x * blockDim.x + threadIdx.x;
    if (i < MROWS) g_best[i] = 0ULL;
}

// ---------------- kernel 1: normalize emb rows, compute t = emb_n . b_in ---
__global__ void norm_emb_kernel(const float4* __restrict__ emb4,
                                const float4* __restrict__ bin4) {
    int row = blockIdx.x;
    int tid = threadIdx.x;              // 128 threads, 4 floats each
    float4 v = emb4[row * 128 + tid];
    float4 bb = bin4[tid];
    float ss = v.x * v.x + v.y * v.y + v.z * v.z + v.w * v.w;
    float db = v.x * bb.x + v.y * bb.y + v.z * bb.z + v.w * bb.w;
    #pragma unroll
    for (int o = 16; o > 0; o >>= 1) {
        ss += __shfl_down_sync(0xffffffffu, ss, o);
        db += __shfl_down_sync(0xffffffffu, db, o);
    }
    __shared__ float sss[4], sdb[4];
    __shared__ float s_scale;
    if ((tid & 31) == 0) { sss[tid >> 5] = ss; sdb[tid >> 5] = db; }
    __syncthreads();
    if (tid == 0) {
        float ts = sss[0] + sss[1] + sss[2] + sss[3];
        float td = sdb[0] + sdb[1] + sdb[2] + sdb[3];
        float scale = 1.0f / fmaxf(sqrtf(ts), 1e-12f);
        s_scale = scale;
        g_t[row] = td * scale;
    }
    __syncthreads();
    float sc = s_scale;
    float4 o;
    o.x = v.x * sc; o.y = v.y * sc; o.z = v.z * sc; o.w = v.w * sc;
    ((float4*)g_embn)[row * 128 + tid] = o;
}

// ---------------- kernel 2: M = emb_n (8192x512) @ W_in (512x512)  [NN] ----
__global__ __launch_bounds__(NTHREADS) void gemm_M_kernel(const float* __restrict__ Win) {
    __shared__ float As[BKK][BM + 4];
    __shared__ float Bs[BKK][BN + 4];
    int tid = threadIdx.x, tx = tid & 15, ty = tid >> 4;
    int mBase = blockIdx.y * BM;
    const float4* A4 = (const float4*)g_embn;
    const float4* B4 = (const float4*)Win;

    unsigned long long acc[8][4];
    #pragma unroll
    for (int i = 0; i < 8; i++)
        #pragma unroll
        for (int p = 0; p < 4; p++) acc[i][p] = 0ULL;

    for (int kb = 0; kb < EDIM / BKK; kb++) {
        #pragma unroll
        for (int r = 0; r < 2; r++) {                 // A: transpose-load
            int li = tid + r * 256;
            int row = li >> 2, c4 = li & 3;
            float4 v = A4[(mBase + row) * 128 + kb * 4 + c4];
            As[c4 * 4 + 0][row] = v.x; As[c4 * 4 + 1][row] = v.y;
            As[c4 * 4 + 2][row] = v.z; As[c4 * 4 + 3][row] = v.w;
        }
        #pragma unroll
        for (int r = 0; r < 2; r++) {                 // B: direct k-major load
            int li = tid + r * 256;
            int rk = li >> 5, n4 = li & 31;
            float4 v = B4[(kb * BKK + rk) * 128 + blockIdx.x * 32 + n4];
            *(float4*)&Bs[rk][n4 * 4] = v;
        }
        __syncthreads();
        #pragma unroll
        for (int k = 0; k < BKK; k++) {
            float4 a0 = *(const float4*)&As[k][ty * 8];
            float4 a1 = *(const float4*)&As[k][ty * 8 + 4];
            float4 b0 = *(const float4*)&Bs[k][tx * 8];
            float4 b1 = *(const float4*)&Bs[k][tx * 8 + 4];
            float av[8] = {a0.x, a0.y, a0.z, a0.w, a1.x, a1.y, a1.z, a1.w};
            unsigned long long bp[4] = {pk2(b0.x, b0.y), pk2(b0.z, b0.w),
                                        pk2(b1.x, b1.y), pk2(b1.z, b1.w)};
            #pragma unroll
            for (int i = 0; i < 8; i++) {
                unsigned long long ap = pk2(av[i], av[i]);
                #pragma unroll
                for (int p = 0; p < 4; p++) fma2(acc[i][p], ap, bp[p]);
            }
        }
        __syncthreads();
    }
    int nBase = blockIdx.x * BN;
    #pragma unroll
    for (int i = 0; i < 8; i++) {
        int m = mBase + ty * 8 + i;
        #pragma unroll
        for (int p = 0; p < 4; p++) {
            g_M[m * LATENT + nBase + tx * 8 + 2 * p]     = lo32(acc[i][p]);
            g_M[m * LATENT + nBase + tx * 8 + 2 * p + 1] = hi32(acc[i][p]);
        }
    }
}

// ---------------- kernel 3: scores = z @ M^T + t, fused argmax  [NT] -------
__global__ __launch_bounds__(NTHREADS) void gemm_scores_kernel(const float* __restrict__ z) {
    __shared__ float As[BKK][BM + 4];
    __shared__ float Bs[BKK][BN + 4];
    __shared__ unsigned long long red[BM][16];
    int tid = threadIdx.x, tx = tid & 15, ty = tid >> 4;
    int mBase = blockIdx.y * BM;
    int nBase = blockIdx.x * BN;
    const float4* A4 = (const float4*)z;
    const float4* B4 = (const float4*)g_M;

    unsigned long long acc[8][4];
    #pragma unroll
    for (int i = 0; i < 8; i++)
        #pragma unroll
        for (int p = 0; p < 4; p++) acc[i][p] = 0ULL;

    for (int kb = 0; kb < LATENT / BKK; kb++) {
        #pragma unroll
        for (int r = 0; r < 2; r++) {                 // A rows (m), k-contig
            int li = tid + r * 256;
            int row = li >> 2, c4 = li & 3;
            float4 v = A4[(mBase + row) * 128 + kb * 4 + c4];
            As[c4 * 4 + 0][row] = v.x; As[c4 * 4 + 1][row] = v.y;
            As[c4 * 4 + 2][row] = v.z; As[c4 * 4 + 3][row] = v.w;
        }
        #pragma unroll
        for (int r = 0; r < 2; r++) {                 // B rows (n), k-contig
            int li = tid + r * 256;
            int row = li >> 2, c4 = li & 3;
            float4 v = B4[(nBase + row) * 128 + kb * 4 + c4];
            Bs[c4 * 4 + 0][row] = v.x; Bs[c4 * 4 + 1][row] = v.y;
            Bs[c4 * 4 + 2][row] = v.z; Bs[c4 * 4 + 3][row] = v.w;
        }
        __syncthreads();
        #pragma unroll
        for (int k = 0; k < BKK; k++) {
            float4 a0 = *(const float4*)&As[k][ty * 8];
            float4 a1 = *(const float4*)&As[k][ty * 8 + 4];
            float4 b0 = *(const float4*)&Bs[k][tx * 8];
            float4 b1 = *(const float4*)&Bs[k][tx * 8 + 4];
            float av[8] = {a0.x, a0.y, a0.z, a0.w, a1.x, a1.y, a1.z, a1.w};
            unsigned long long bp[4] = {pk2(b0.x, b0.y), pk2(b0.z, b0.w),
                                        pk2(b1.x, b1.y), pk2(b1.z, b1.w)};
            #pragma unroll
            for (int i = 0; i < 8; i++) {
                unsigned long long ap = pk2(av[i], av[i]);
                #pragma unroll
                for (int p = 0; p < 4; p++) fma2(acc[i][p], ap, bp[p]);
            }
        }
        __syncthreads();
    }

    // epilogue: add t, per-thread argmax over its 8 columns per row
    float tv[8];
    #pragma unroll
    for (int j = 0; j < 8; j++) tv[j] = g_t[nBase + tx * 8 + j];

    #pragma unroll
    for (int i = 0; i < 8; i++) {
        float c[8];
        #pragma unroll
        for (int p = 0; p < 4; p++) { c[2 * p] = lo32(acc[i][p]); c[2 * p + 1] = hi32(acc[i][p]); }
        float bestv = c[0] + tv[0];
        int bestn = nBase + tx * 8;
        #pragma unroll
        for (int j = 1; j < 8; j++) {
            float s = c[j] + tv[j];
            if (s > bestv) { bestv = s; bestn = nBase + tx * 8 + j; }
        }
        unsigned long long e = ((unsigned long long)float_ord(bestv) << 32)
                             | (unsigned)(NE - 1 - bestn);
        red[ty * 8 + i][tx] = e;
    }
    __syncthreads();
    if (tid < BM) {
        unsigned long long b = red[tid][0];
        #pragma unroll
        for (int c = 1; c < 16; c++) { unsigned long long v = red[tid][c]; if (v > b) b = v; }
        atomicMax(&g_best[mBase + tid], b);
    }
}

// ---------------- kernel 4: extract idx ----------------
__global__ void extract_kernel(float* idx_out) {
    int i = blockIdx.x * blockDim.x + threadIdx.x;
    if (i < MROWS) {
        unsigned long long v = g_best[i];
        int n = (NE - 1) - (int)(unsigned)(v & 0xFFFFFFFFull);
        g_idx[i] = n;
        if (idx_out) idx_out[i] = (float)n;
    }
}

// ---------------- kernel 5: z_q = emb_n[idx] @ W_out^T + b_out  [NT+gather] -
__global__ __launch_bounds__(NTHREADS) void gemm_out_kernel(const float* __restrict__ Wout,
                                                            const float* __restrict__ bout,
                                                            float* __restrict__ zq) {
    __shared__ float As[BKK][BM + 4];
    __shared__ float Bs[BKK][BN + 4];
    __shared__ int sIdx[BM];
    int tid = threadIdx.x, tx = tid & 15, ty = tid >> 4;
    int mBase = blockIdx.y * BM;
    int nBase = blockIdx.x * BN;
    const float4* A4 = (const float4*)g_embn;
    const float4* B4 = (const float4*)Wout;

    if (tid < BM) sIdx[tid] = g_idx[mBase + tid];
    __syncthreads();

    unsigned long long acc[8][4];
    #pragma unroll
    for (int i = 0; i < 8; i++)
        #pragma unroll
        for (int p = 0; p < 4; p++) acc[i][p] = 0ULL;

    for (int kb = 0; kb < EDIM / BKK; kb++) {
        #pragma unroll
        for (int r = 0; r < 2; r++) {                 // A: gathered rows
            int li = tid + r * 256;
            int row = li >> 2, c4 = li & 3;
            float4 v = A4[sIdx[row] * 128 + kb * 4 + c4];
            As[c4 * 4 + 0][row] = v.x; As[c4 * 4 + 1][row] = v.y;
            As[c4 * 4 + 2][row] = v.z; As[c4 * 4 + 3][row] = v.w;
        }
        #pragma unroll
        for (int r = 0; r < 2; r++) {                 // B rows (n), k-contig
            int li = tid + r * 256;
            int row = li >> 2, c4 = li & 3;
            float4 v = B4[(nBase + row) * 128 + kb * 4 + c4];
            Bs[c4 * 4 + 0][row] = v.x; Bs[c4 * 4 + 1][row] = v.y;
            Bs[c4 * 4 + 2][row] = v.z; Bs[c4 * 4 + 3][row] = v.w;
        }
        __syncthreads();
        #pragma unroll
        for (int k = 0; k < BKK; k++) {
            float4 a0 = *(const float4*)&As[k][ty * 8];
            float4 a1 = *(const float4*)&As[k][ty * 8 + 4];
            float4 b0 = *(const float4*)&Bs[k][tx * 8];
            float4 b1 = *(const float4*)&Bs[k][tx * 8 + 4];
            float av[8] = {a0.x, a0.y, a0.z, a0.w, a1.x, a1.y, a1.z, a1.w};
            unsigned long long bp[4] = {pk2(b0.x, b0.y), pk2(b0.z, b0.w),
                                        pk2(b1.x, b1.y), pk2(b1.z, b1.w)};
            #pragma unroll
            for (int i = 0; i < 8; i++) {
                unsigned long long ap = pk2(av[i], av[i]);
                #pragma unroll
                for (int p = 0; p < 4; p++) fma2(acc[i][p], ap, bp[p]);
            }
        }
        __syncthreads();
    }
    #pragma unroll
    for (int i = 0; i < 8; i++) {
        int m = mBase + ty * 8 + i;
        #pragma unroll
        for (int p = 0; p < 4; p++) {
            int n0 = nBase + tx * 8 + 2 * p;
            zq[m * LATENT + n0]     = lo32(acc[i][p]) + bout[n0];
            zq[m * LATENT + n0 + 1] = hi32(acc[i][p]) + bout[n0 + 1];
        }
    }
}

// ---------------- host launcher ----------------
extern "C" void kernel_launch(void* const* d_in, const int* in_sizes, int n_in,
                              void* d_out, int out_size) {
    const float* z     = (const float*)d_in[0];
    // d_in[1] = mask (unused by reference)
    const float* W_in  = (const float*)d_in[2];
    const float* b_in  = (const float*)d_in[3];
    const float* W_out = (const float*)d_in[4];
    const float* b_out = (const float*)d_in[5];
    const float* emb   = (const float*)d_in[6];
    float* out = (float*)d_out;

    const long long ZQ = (long long)MROWS * LATENT;  // 8388608
    float* zq_ptr  = nullptr;
    float* idx_ptr = nullptr;
    if ((long long)out_size >= ZQ + MROWS)      { zq_ptr = out; idx_ptr = out + ZQ; }
    else if ((long long)out_size >= ZQ)         { zq_ptr = out; }
    else if (out_size == MROWS)                 { idx_ptr = out; }

    init_best_kernel<<<(MROWS + 255) / 256, 256>>>();
    norm_emb_kernel<<<NE, 128>>>((const float4*)emb, (const float4*)b_in);
    gemm_M_kernel<<<dim3(LATENT / BN, NE / BM), NTHREADS>>>(W_in);
    gemm_scores_kernel<<<dim3(NE / BN, MROWS / BM), NTHREADS>>>(z);
    extract_kernel<<<(MROWS + 255) / 256, 256>>>(idx_ptr);
    if (zq_ptr)
        gemm_out_kernel<<<dim3(LATENT / BN, MROWS / BM), NTHREADS>>>(W_out, b_out, zq_ptr);
}

// round 5
// speedup vs baseline: 2.0061x; 2.0061x over previous
#include <cuda_runtime.h>
#include <cuda_bf16.h>
#include <cstdint>
#include <math.h>

// Problem constants
#define MROWS 16384   // B*S
#define LATENT 512
#define EDIM 512
#define NE 8192

// SIMT GEMM tiling (gemm_M / gemm_out)
#define BM 128
#define BN 128
#define BKK 16
#define NTHREADS 256

// mma.sync scores tiling
#define SB_M 128
#define SB_N 128
#define SB_K 32
#define NKIT (LATENT / SB_K)        // 16
#define NTILES (NE / SB_N)          // 64 tiles per row
#define NCAND (2 * NTILES)          // 128 candidates per row

// smem stage layout (bytes): 4 arrays of 128 rows x 80B (32 halves + 8 pad)
#define ROWB 80
#define ARR_BYTES (128 * ROWB)      // 10240
#define OFF_AH 0
#define OFF_AL (1 * ARR_BYTES)
#define OFF_BH (2 * ARR_BYTES)
#define OFF_BL (3 * ARR_BYTES)
#define STAGE_BYTES (4 * ARR_BYTES) // 40960
#define DYN_SMEM (2 * STAGE_BYTES)  // 81920

// ---------------- device scratch (static, allocation-free) ----------------
__device__ float g_embn[NE * EDIM];                 // normalized embedding
__device__ float g_M[NE * LATENT];                  // M = emb_n @ W_in (fp32, rescore)
__device__ float g_t[NE];                           // t = emb_n . b_in
__device__ __nv_bfloat16 g_zh[MROWS * LATENT];      // z hi split
__device__ __nv_bfloat16 g_zl[MROWS * LATENT];      // z lo split
__device__ __nv_bfloat16 g_mh[NE * LATENT];         // M hi split
__device__ __nv_bfloat16 g_ml[NE * LATENT];         // M lo split
__device__ unsigned long long g_cand2[MROWS * NCAND];  // per (row,tile) top-2 packed
__device__ int g_idx[MROWS];

// ---------------- helpers ----------------
__device__ __forceinline__ uint32_t smem_u32(const void* p) {
    uint32_t a;
    asm("{ .reg .u64 t; cvta.to.shared.u64 t, %1; cvt.u32.u64 %0, t; }" : "=r"(a) : "l"(p));
    return a;
}
#define CP_ASYNC16(dst32, src) \
    asm volatile("cp.async.cg.shared.global [%0], [%1], 16;" :: "r"(dst32), "l"(src))
#define CP_COMMIT() asm volatile("cp.async.commit_group;" ::: "memory")
#define CP_WAIT1()  asm volatile("cp.async.wait_group 1;" ::: "memory")
#define CP_WAIT0()  asm volatile("cp.async.wait_group 0;" ::: "memory")

__device__ __forceinline__ void mma_bf16(float* d, const uint32_t* a, const uint32_t* b) {
    asm volatile(
        "mma.sync.aligned.m16n8k16.row.col.f32.bf16.bf16.f32 "
        "{%0,%1,%2,%3}, {%4,%5,%6,%7}, {%8,%9}, {%0,%1,%2,%3};"
        : "+f"(d[0]), "+f"(d[1]), "+f"(d[2]), "+f"(d[3])
        : "r"(a[0]), "r"(a[1]), "r"(a[2]), "r"(a[3]), "r"(b[0]), "r"(b[1]));
}

// f32x2 helpers (SIMT GEMMs)
__device__ __forceinline__ unsigned long long pk2(float lo, float hi) {
    unsigned long long r;
    asm("mov.b64 %0, {%1, %2};" : "=l"(r) : "f"(lo), "f"(hi));
    return r;
}
__device__ __forceinline__ void fma2(unsigned long long& d, unsigned long long a, unsigned long long b) {
    asm("fma.rn.f32x2 %0, %1, %2, %0;" : "+l"(d) : "l"(a), "l"(b));
}
__device__ __forceinline__ float lo32(unsigned long long v) { return __uint_as_float((unsigned)v); }
__device__ __forceinline__ float hi32(unsigned long long v) { return __uint_as_float((unsigned)(v >> 32)); }
__device__ __forceinline__ unsigned float_ord(float f) {
    unsigned u = __float_as_uint(f);
    return (u & 0x80000000u) ? ~u : (u | 0x80000000u);
}
__device__ __forceinline__ unsigned long long umax64(unsigned long long a, unsigned long long b) {
    return a > b ? a : b;
}
__device__ __forceinline__ unsigned long long umin64(unsigned long long a, unsigned long long b) {
    return a < b ? a : b;
}

// ---------------- kernel: normalize emb rows, t = emb_n . b_in ----------------
__global__ void norm_emb_kernel(const float4* __restrict__ emb4,
                                const float4* __restrict__ bin4) {
    int row = blockIdx.x;
    int tid = threadIdx.x;              // 128 threads, 4 floats each
    float4 v = emb4[row * 128 + tid];
    float4 bb = bin4[tid];
    float ss = v.x * v.x + v.y * v.y + v.z * v.z + v.w * v.w;
    float db = v.x * bb.x + v.y * bb.y + v.z * bb.z + v.w * bb.w;
    #pragma unroll
    for (int o = 16; o > 0; o >>= 1) {
        ss += __shfl_down_sync(0xffffffffu, ss, o);
        db += __shfl_down_sync(0xffffffffu, db, o);
    }
    __shared__ float sss[4], sdb[4];
    __shared__ float s_scale;
    if ((tid & 31) == 0) { sss[tid >> 5] = ss; sdb[tid >> 5] = db; }
    __syncthreads();
    if (tid == 0) {
        float ts = sss[0] + sss[1] + sss[2] + sss[3];
        float td = sdb[0] + sdb[1] + sdb[2] + sdb[3];
        float scale = 1.0f / fmaxf(sqrtf(ts), 1e-12f);
        s_scale = scale;
        g_t[row] = td * scale;
    }
    __syncthreads();
    float sc = s_scale;
    float4 o;
    o.x = v.x * sc; o.y = v.y * sc; o.z = v.z * sc; o.w = v.w * sc;
    ((float4*)g_embn)[row * 128 + tid] = o;
}

// ---------------- kernel: split z into bf16 hi/lo ----------------
__global__ void split_z_kernel(const float4* __restrict__ z4) {
    int i = blockIdx.x * blockDim.x + threadIdx.x;   // over float4s
    float4 v = z4[i];
    __nv_bfloat16 h0 = __float2bfloat16(v.x), h1 = __float2bfloat16(v.y);
    __nv_bfloat16 h2 = __float2bfloat16(v.z), h3 = __float2bfloat16(v.w);
    __nv_bfloat162* zh2 = (__nv_bfloat162*)g_zh;
    __nv_bfloat162* zl2 = (__nv_bfloat162*)g_zl;
    zh2[2 * i]     = __nv_bfloat162(h0, h1);
    zh2[2 * i + 1] = __nv_bfloat162(h2, h3);
    zl2[2 * i]     = __nv_bfloat162(__float2bfloat16(v.x - __bfloat162float(h0)),
                                    __float2bfloat16(v.y - __bfloat162float(h1)));
    zl2[2 * i + 1] = __nv_bfloat162(__float2bfloat16(v.z - __bfloat162float(h2)),
                                    __float2bfloat16(v.w - __bfloat162float(h3)));
}

// ---------------- kernel: M = emb_n @ W_in [NN], epilogue splits to bf16 ----
__global__ __launch_bounds__(NTHREADS) void gemm_M_kernel(const float* __restrict__ Win) {
    __shared__ float As[BKK][BM + 4];
    __shared__ float Bs[BKK][BN + 4];
    int tid = threadIdx.x, tx = tid & 15, ty = tid >> 4;
    int mBase = blockIdx.y * BM;
    const float4* A4 = (const float4*)g_embn;
    const float4* B4 = (const float4*)Win;

    unsigned long long acc[8][4];
    #pragma unroll
    for (int i = 0; i < 8; i++)
        #pragma unroll
        for (int p = 0; p < 4; p++) acc[i][p] = 0ULL;

    for (int kb = 0; kb < EDIM / BKK; kb++) {
        #pragma unroll
        for (int r = 0; r < 2; r++) {                 // A: transpose-load
            int li = tid + r * 256;
            int row = li >> 2, c4 = li & 3;
            float4 v = A4[(mBase + row) * 128 + kb * 4 + c4];
            As[c4 * 4 + 0][row] = v.x; As[c4 * 4 + 1][row] = v.y;
            As[c4 * 4 + 2][row] = v.z; As[c4 * 4 + 3][row] = v.w;
        }
        #pragma unroll
        for (int r = 0; r < 2; r++) {                 // B: direct k-major load
            int li = tid + r * 256;
            int rk = li >> 5, n4 = li & 31;
            float4 v = B4[(kb * BKK + rk) * 128 + blockIdx.x * 32 + n4];
            *(float4*)&Bs[rk][n4 * 4] = v;
        }
        __syncthreads();
        #pragma unroll
        for (int k = 0; k < BKK; k++) {
            float4 a0 = *(const float4*)&As[k][ty * 8];
            float4 a1 = *(const float4*)&As[k][ty * 8 + 4];
            float4 b0 = *(const float4*)&Bs[k][tx * 8];
            float4 b1 = *(const float4*)&Bs[k][tx * 8 + 4];
            float av[8] = {a0.x, a0.y, a0.z, a0.w, a1.x, a1.y, a1.z, a1.w};
            unsigned long long bp[4] = {pk2(b0.x, b0.y), pk2(b0.z, b0.w),
                                        pk2(b1.x, b1.y), pk2(b1.z, b1.w)};
            #pragma unroll
            for (int i = 0; i < 8; i++) {
                unsigned long long ap = pk2(av[i], av[i]);
                #pragma unroll
                for (int p = 0; p < 4; p++) fma2(acc[i][p], ap, bp[p]);
            }
        }
        __syncthreads();
    }
    int nBase = blockIdx.x * BN;
    #pragma unroll
    for (int i = 0; i < 8; i++) {
        int m = mBase + ty * 8 + i;
        #pragma unroll
        for (int p = 0; p < 4; p++) {
            #pragma unroll
            for (int q = 0; q < 2; q++) {
                float v = q ? hi32(acc[i][p]) : lo32(acc[i][p]);
                int col = nBase + tx * 8 + 2 * p + q;
                g_M[m * LATENT + col] = v;
                __nv_bfloat16 h = __float2bfloat16(v);
                g_mh[m * LATENT + col] = h;
                g_ml[m * LATENT + col] = __float2bfloat16(v - __bfloat162float(h));
            }
        }
    }
}

// ---------------- kernel: scores via mma.sync (bf16 x3) + top-2/tile --------
__global__ __launch_bounds__(256) void scores_mma_kernel() {
    extern __shared__ char dyn[];
    __shared__ float t_s[SB_N];
    __shared__ unsigned long long red[SB_M][4][2];

    int tid = threadIdx.x;
    int wid = tid >> 5, lane = tid & 31;
    int wm = wid >> 2, wn = wid & 3;           // 2 x 4 warp grid
    int g = lane >> 2, q = lane & 3;
    int mBase = blockIdx.y * SB_M;
    int nBase = blockIdx.x * SB_N;

    uint32_t sb = smem_u32(dyn);
    if (tid < SB_N) t_s[tid] = g_t[nBase + tid];

    const char* pzh = (const char*)g_zh;
    const char* pzl = (const char*)g_zl;
    const char* pmh = (const char*)g_mh;
    const char* pml = (const char*)g_ml;

    float acc[4][4][4];
    #pragma unroll
    for (int t = 0; t < 4; t++)
        #pragma unroll
        for (int n = 0; n < 4; n++)
            #pragma unroll
            for (int e = 0; e < 4; e++) acc[t][n][e] = 0.0f;

    // stage loader (8 x cp.async.16 per thread)
    auto load_stage = [&](int s, int kb) {
        uint32_t sbase = sb + s * STAGE_BYTES;
        #pragma unroll
        for (int r = 0; r < 2; r++) {
            int li = tid + r * 256;
            int row = li >> 2, c = li & 3;
            uint32_t soff = (uint32_t)(row * ROWB + c * 16);
            size_t gA = (size_t)(mBase + row) * 1024 + (size_t)kb * 64 + c * 16;
            size_t gB = (size_t)(nBase + row) * 1024 + (size_t)kb * 64 + c * 16;
            CP_ASYNC16(sbase + OFF_AH + soff, pzh + gA);
            CP_ASYNC16(sbase + OFF_AL + soff, pzl + gA);
            CP_ASYNC16(sbase + OFF_BH + soff, pmh + gB);
            CP_ASYNC16(sbase + OFF_BL + soff, pml + gB);
        }
        CP_COMMIT();
    };

    load_stage(0, 0);

    for (int kb = 0; kb < NKIT; kb++) {
        int s = kb & 1;
        if (kb + 1 < NKIT) load_stage(s ^ 1, kb + 1);
        if (kb + 1 < NKIT) { CP_WAIT1(); } else { CP_WAIT0(); }
        __syncthreads();

        const char* st = dyn + s * STAGE_BYTES;
        #pragma unroll
        for (int kk = 0; kk < 2; kk++) {
            int kbyte = kk * 32 + q * 4;     // byte offset of this lane's k-pair
            uint32_t ah[4][4], al[4][4], bh[4][2], bl[4][2];
            #pragma unroll
            for (int t = 0; t < 4; t++) {
                int r0 = wm * 64 + t * 16 + g;
                const char* a0 = st + OFF_AH + r0 * ROWB + kbyte;
                const char* a8 = st + OFF_AH + (r0 + 8) * ROWB + kbyte;
                ah[t][0] = *(const uint32_t*)(a0);
                ah[t][1] = *(const uint32_t*)(a8);
                ah[t][2] = *(const uint32_t*)(a0 + 16);
                ah[t][3] = *(const uint32_t*)(a8 + 16);
                const char* l0 = st + OFF_AL + r0 * ROWB + kbyte;
                const char* l8 = st + OFF_AL + (r0 + 8) * ROWB + kbyte;
                al[t][0] = *(const uint32_t*)(l0);
                al[t][1] = *(const uint32_t*)(l8);
                al[t][2] = *(const uint32_t*)(l0 + 16);
                al[t][3] = *(const uint32_t*)(l8 + 16);
            }
            #pragma unroll
            for (int nt = 0; nt < 4; nt++) {
                int n0 = wn * 32 + nt * 8 + g;
                const char* b0 = st + OFF_BH + n0 * ROWB + kbyte;
                bh[nt][0] = *(const uint32_t*)(b0);
                bh[nt][1] = *(const uint32_t*)(b0 + 16);
                const char* c0 = st + OFF_BL + n0 * ROWB + kbyte;
                bl[nt][0] = *(const uint32_t*)(c0);
                bl[nt][1] = *(const uint32_t*)(c0 + 16);
            }
            #pragma unroll
            for (int t = 0; t < 4; t++)
                #pragma unroll
                for (int nt = 0; nt < 4; nt++) {
                    mma_bf16(acc[t][nt], ah[t], bh[nt]);
                    mma_bf16(acc[t][nt], ah[t], bl[nt]);
                    mma_bf16(acc[t][nt], al[t], bh[nt]);
                }
        }
        __syncthreads();
    }

    // epilogue: bias + per-(lane,row) top-2, quad merge, cross-warp merge
    #pragma unroll
    for (int t = 0; t < 4; t++) {
        #pragma unroll
        for (int h = 0; h < 2; h++) {
            float v1 = -3.4e38f, v2 = -3.4e38f;
            int i1 = 0, i2 = 0;
            #pragma unroll
            for (int nt = 0; nt < 4; nt++)
                #pragma unroll
                for (int j = 0; j < 2; j++) {
                    int cloc = wn * 32 + nt * 8 + q * 2 + j;
                    float sval = acc[t][nt][h * 2 + j] + t_s[cloc];
                    int n = nBase + cloc;
                    if (sval > v1) { v2 = v1; i2 = i1; v1 = sval; i1 = n; }
                    else if (sval > v2) { v2 = sval; i2 = n; }
                }
            unsigned long long e1 = ((unsigned long long)float_ord(v1) << 32)
                                  | (unsigned)(NE - 1 - i1);
            unsigned long long e2 = ((unsigned long long)float_ord(v2) << 32)
                                  | (unsigned)(NE - 1 - i2);
            #pragma unroll
            for (int off = 2; off >= 1; off >>= 1) {
                unsigned long long o1 = __shfl_down_sync(0xffffffffu, e1, off);
                unsigned long long o2 = __shfl_down_sync(0xffffffffu, e2, off);
                unsigned long long n1 = umax64(e1, o1);
                unsigned long long n2 = umax64(umin64(e1, o1), umax64(e2, o2));
                e1 = n1; e2 = n2;
            }
            if (q == 0) {
                int row = wm * 64 + t * 16 + g + h * 8;
                red[row][wn][0] = e1;
                red[row][wn][1] = e2;
            }
        }
    }
    __syncthreads();
    if (tid < SB_M) {
        unsigned long long b1 = 0, b2 = 0;
        #pragma unroll
        for (int w = 0; w < 4; w++) {
            #pragma unroll
            for (int j = 0; j < 2; j++) {
                unsigned long long e = red[tid][w][j];
                if (e > b1) { b2 = b1; b1 = e; }
                else if (e > b2) { b2 = e; }
            }
        }
        size_t base = (size_t)(mBase + tid) * NCAND + blockIdx.x * 2;
        g_cand2[base]     = b1;
        g_cand2[base + 1] = b2;
    }
}

// ---------------- kernel: approx top-8 of 128 candidates + exact rescore ----
__global__ __launch_bounds__(256) void rescore_kernel(const float* __restrict__ z,
                                                      float* __restrict__ idx_out) {
    int row = blockIdx.x * 8 + (threadIdx.x >> 5);
    int lane = threadIdx.x & 31;
    if (row >= MROWS) return;

    float zr[16];
    #pragma unroll
    for (int i = 0; i < 16; i++) zr[i] = z[(size_t)row * LATENT + i * 32 + lane];

    unsigned long long e[4];
    #pragma unroll
    for (int j = 0; j < 4; j++) e[j] = g_cand2[(size_t)row * NCAND + lane + j * 32];

    float bv = -3.4e38f;
    int bn = 0x7fffffff;
    #pragma unroll 1
    for (int it = 0; it < 8; it++) {
        unsigned long long m = e[0];
        #pragma unroll
        for (int j = 1; j < 4; j++) m = umax64(m, e[j]);
        #pragma unroll
        for (int off = 16; off > 0; off >>= 1)
            m = umax64(m, __shfl_xor_sync(0xffffffffu, m, off));
        #pragma unroll
        for (int j = 0; j < 4; j++) if (e[j] == m) e[j] = 0ULL;

        int n = (NE - 1) - (int)(unsigned)(m & 0xFFFFFFFFull);
        const float* Mr = g_M + (size_t)n * LATENT;
        float p = 0.0f;
        #pragma unroll
        for (int i = 0; i < 16; i++) p = fmaf(zr[i], Mr[i * 32 + lane], p);
        #pragma unroll
        for (int off = 16; off > 0; off >>= 1)
            p += __shfl_xor_sync(0xffffffffu, p, off);
        float s = p + g_t[n];
        if (s > bv || (s == bv && n < bn)) { bv = s; bn = n; }
    }
    if (lane == 0) {
        g_idx[row] = bn;
        if (idx_out) idx_out[row] = (float)bn;
    }
}

// ---------------- kernel: z_q = emb_n[idx] @ W_out^T + b_out  [NT+gather] ----
__global__ __launch_bounds__(NTHREADS) void gemm_out_kernel(const float* __restrict__ Wout,
                                                            const float* __restrict__ bout,
                                                            float* __restrict__ zq) {
    __shared__ float As[BKK][BM + 4];
    __shared__ float Bs[BKK][BN + 4];
    __shared__ int sIdx[BM];
    int tid = threadIdx.x, tx = tid & 15, ty = tid >> 4;
    int mBase = blockIdx.y * BM;
    int nBase = blockIdx.x * BN;
    const float4* A4 = (const float4*)g_embn;
    const float4* B4 = (const float4*)Wout;

    if (tid < BM) sIdx[tid] = g_idx[mBase + tid];
    __syncthreads();

    unsigned long long acc[8][4];
    #pragma unroll
    for (int i = 0; i < 8; i++)
        #pragma unroll
        for (int p = 0; p < 4; p++) acc[i][p] = 0ULL;

    for (int kb = 0; kb < EDIM / BKK; kb++) {
        #pragma unroll
        for (int r = 0; r < 2; r++) {                 // A: gathered rows
            int li = tid + r * 256;
            int row = li >> 2, c4 = li & 3;
            float4 v = A4[sIdx[row] * 128 + kb * 4 + c4];
            As[c4 * 4 + 0][row] = v.x; As[c4 * 4 + 1][row] = v.y;
            As[c4 * 4 + 2][row] = v.z; As[c4 * 4 + 3][row] = v.w;
        }
        #pragma unroll
        for (int r = 0; r < 2; r++) {                 // B rows (n), k-contig
            int li = tid + r * 256;
            int row = li >> 2, c4 = li & 3;
            float4 v = B4[(nBase + row) * 128 + kb * 4 + c4];
            Bs[c4 * 4 + 0][row] = v.x; Bs[c4 * 4 + 1][row] = v.y;
            Bs[c4 * 4 + 2][row] = v.z; Bs[c4 * 4 + 3][row] = v.w;
        }
        __syncthreads();
        #pragma unroll
        for (int k = 0; k < BKK; k++) {
            float4 a0 = *(const float4*)&As[k][ty * 8];
            float4 a1 = *(const float4*)&As[k][ty * 8 + 4];
            float4 b0 = *(const float4*)&Bs[k][tx * 8];
            float4 b1 = *(const float4*)&Bs[k][tx * 8 + 4];
            float av[8] = {a0.x, a0.y, a0.z, a0.w, a1.x, a1.y, a1.z, a1.w};
            unsigned long long bp[4] = {pk2(b0.x, b0.y), pk2(b0.z, b0.w),
                                        pk2(b1.x, b1.y), pk2(b1.z, b1.w)};
            #pragma unroll
            for (int i = 0; i < 8; i++) {
                unsigned long long ap = pk2(av[i], av[i]);
                #pragma unroll
                for (int p = 0; p < 4; p++) fma2(acc[i][p], ap, bp[p]);
            }
        }
        __syncthreads();
    }
    #pragma unroll
    for (int i = 0; i < 8; i++) {
        int m = mBase + ty * 8 + i;
        #pragma unroll
        for (int p = 0; p < 4; p++) {
            int n0 = nBase + tx * 8 + 2 * p;
            zq[m * LATENT + n0]     = lo32(acc[i][p]) + bout[n0];
            zq[m * LATENT + n0 + 1] = hi32(acc[i][p]) + bout[n0 + 1];
        }
    }
}

// ---------------- host launcher ----------------
extern "C" void kernel_launch(void* const* d_in, const int* in_sizes, int n_in,
                              void* d_out, int out_size) {
    const float* z     = (const float*)d_in[0];
    // d_in[1] = mask (unused by reference)
    const float* W_in  = (const float*)d_in[2];
    const float* b_in  = (const float*)d_in[3];
    const float* W_out = (const float*)d_in[4];
    const float* b_out = (const float*)d_in[5];
    const float* emb   = (const float*)d_in[6];
    float* out = (float*)d_out;

    const long long ZQ = (long long)MROWS * LATENT;  // 8388608
    float* zq_ptr  = nullptr;
    float* idx_ptr = nullptr;
    if ((long long)out_size >= ZQ + MROWS)      { zq_ptr = out; idx_ptr = out + ZQ; }
    else if ((long long)out_size >= ZQ)         { zq_ptr = out; }
    else if (out_size == MROWS)                 { idx_ptr = out; }

    cudaFuncSetAttribute(scores_mma_kernel,
                         cudaFuncAttributeMaxDynamicSharedMemorySize, DYN_SMEM);

    norm_emb_kernel<<<NE, 128>>>((const float4*)emb, (const float4*)b_in);
    split_z_kernel<<<(MROWS * LATENT / 4) / 256, 256>>>((const float4*)z);
    gemm_M_kernel<<<dim3(LATENT / BN, NE / BM), NTHREADS>>>(W_in);
    scores_mma_kernel<<<dim3(NE / SB_N, MROWS / SB_M), 256, DYN_SMEM>>>();
    rescore_kernel<<<MROWS / 8, 256>>>(z, idx_ptr);
    if (zq_ptr)
        gemm_out_kernel<<<dim3(LATENT / BN, MROWS / BM), NTHREADS>>>(W_out, b_out, zq_ptr);
}

// round 9
// speedup vs baseline: 4.3190x; 2.1529x over previous
#include <cuda_runtime.h>
#include <cuda_bf16.h>
#include <cuda_fp16.h>
#include <cstdint>
#include <math.h>

// Problem constants
#define MROWS 16384   // B*S
#define LATENT 512
#define EDIM 512
#define NE 8192

// SIMT GEMM tiling (gemm_M / gemm_Q)
#define BM 128
#define BN 128
#define BKK 16
#define NTHREADS 256

// fp16 mma scores tiling
#define SB_M 128
#define SB_N 128
#define SB_K 64
#define NKIT (LATENT / SB_K)        // 8
#define NTILES (NE / SB_N)          // 64 tiles per row
#define NCAND (2 * NTILES)          // 128 candidates per row

// smem stage: A 128 rows x 128B + B 128 rows x 128B, XOR chunk swizzle
#define ROWB 128
#define A_BYTES (SB_M * ROWB)       // 16384
#define B_BYTES (SB_N * ROWB)       // 16384
#define OFF_A 0
#define OFF_B A_BYTES
#define STAGE_BYTES (A_BYTES + B_BYTES)   // 32768
#define DYN_SMEM (2 * STAGE_BYTES)        // 65536

// ---------------- device scratch (static, allocation-free) ----------------
__device__ float g_embn[NE * EDIM];                 // normalized embedding
__device__ float g_M[NE * LATENT];                  // M = emb_n @ W_in (fp32, rescore)
__device__ float g_Q[NE * LATENT];                  // Q = emb_n @ W_out^T + b_out
__device__ float g_t[NE];                           // t = emb_n . b_in
__device__ __half g_zf16[MROWS * LATENT];           // z in fp16
__device__ __half g_mf16[NE * LATENT];              // M in fp16
__device__ unsigned long long g_cand2[MROWS * NCAND];  // per (row,tile) top-2 packed
__device__ int g_idx[MROWS];

// ---------------- helpers ----------------
__device__ __forceinline__ uint32_t smem_u32(const void* p) {
    uint32_t a;
    asm("{ .reg .u64 t; cvta.to.shared.u64 t, %1; cvt.u32.u64 %0, t; }" : "=r"(a) : "l"(p));
    return a;
}
#define CP_ASYNC16(dst32, src) \
    asm volatile("cp.async.cg.shared.global [%0], [%1], 16;" :: "r"(dst32), "l"(src))
#define CP_COMMIT() asm volatile("cp.async.commit_group;" ::: "memory")
#define CP_WAIT1()  asm volatile("cp.async.wait_group 1;" ::: "memory")
#define CP_WAIT0()  asm volatile("cp.async.wait_group 0;" ::: "memory")

__device__ __forceinline__ void mma_f16(float* d, const uint32_t* a, const uint32_t* b) {
    asm volatile(
        "mma.sync.aligned.m16n8k16.row.col.f32.f16.f16.f32 "
        "{%0,%1,%2,%3}, {%4,%5,%6,%7}, {%8,%9}, {%0,%1,%2,%3};"
        : "+f"(d[0]), "+f"(d[1]), "+f"(d[2]), "+f"(d[3])
        : "r"(a[0]), "r"(a[1]), "r"(a[2]), "r"(a[3]), "r"(b[0]), "r"(b[1]));
}

// f32x2 helpers (SIMT GEMMs)
__device__ __forceinline__ unsigned long long pk2(float lo, float hi) {
    unsigned long long r;
    asm("mov.b64 %0, {%1, %2};" : "=l"(r) : "f"(lo), "f"(hi));
    return r;
}
__device__ __forceinline__ void fma2(unsigned long long& d, unsigned long long a, unsigned long long b) {
    asm("fma.rn.f32x2 %0, %1, %2, %0;" : "+l"(d) : "l"(a), "l"(b));
}
__device__ __forceinline__ float lo32(unsigned long long v) { return __uint_as_float((unsigned)v); }
__device__ __forceinline__ float hi32(unsigned long long v) { return __uint_as_float((unsigned)(v >> 32)); }
__device__ __forceinline__ unsigned float_ord(float f) {
    unsigned u = __float_as_uint(f);
    return (u & 0x80000000u) ? ~u : (u | 0x80000000u);
}
__device__ __forceinline__ unsigned long long umax64(unsigned long long a, unsigned long long b) {
    return a > b ? a : b;
}
__device__ __forceinline__ unsigned long long umin64(unsigned long long a, unsigned long long b) {
    return a < b ? a : b;
}

// ---------------- kernel: normalize emb rows, t = emb_n . b_in ----------------
__global__ void norm_emb_kernel(const float4* __restrict__ emb4,
                                const float4* __restrict__ bin4) {
    int row = blockIdx.x;
    int tid = threadIdx.x;              // 128 threads, 4 floats each
    float4 v = emb4[row * 128 + tid];
    float4 bb = bin4[tid];
    float ss = v.x * v.x + v.y * v.y + v.z * v.z + v.w * v.w;
    float db = v.x * bb.x + v.y * bb.y + v.z * bb.z + v.w * bb.w;
    #pragma unroll
    for (int o = 16; o > 0; o >>= 1) {
        ss += __shfl_down_sync(0xffffffffu, ss, o);
        db += __shfl_down_sync(0xffffffffu, db, o);
    }
    __shared__ float sss[4], sdb[4];
    __shared__ float s_scale;
    if ((tid & 31) == 0) { sss[tid >> 5] = ss; sdb[tid >> 5] = db; }
    __syncthreads();
    if (tid == 0) {
        float ts = sss[0] + sss[1] + sss[2] + sss[3];
        float td = sdb[0] + sdb[1] + sdb[2] + sdb[3];
        float scale = 1.0f / fmaxf(sqrtf(ts), 1e-12f);
        s_scale = scale;
        g_t[row] = td * scale;
    }
    __syncthreads();
    float sc = s_scale;
    float4 o;
    o.x = v.x * sc; o.y = v.y * sc; o.z = v.z * sc; o.w = v.w * sc;
    ((float4*)g_embn)[row * 128 + tid] = o;
}

// ---------------- kernel: convert z to fp16 ----------------
__global__ void conv_z_kernel(const float4* __restrict__ z4) {
    int i = blockIdx.x * blockDim.x + threadIdx.x;   // over float4s
    float4 v = z4[i];
    __half2* o = (__half2*)g_zf16;
    o[2 * i]     = __floats2half2_rn(v.x, v.y);
    o[2 * i + 1] = __floats2half2_rn(v.z, v.w);
}

// ---------------- kernel: M = emb_n @ W_in [NN], epilogue writes fp32+fp16 --
__global__ __launch_bounds__(NTHREADS) void gemm_M_kernel(const float* __restrict__ Win) {
    __shared__ float As[BKK][BM + 4];
    __shared__ float Bs[BKK][BN + 4];
    int tid = threadIdx.x, tx = tid & 15, ty = tid >> 4;
    int mBase = blockIdx.y * BM;
    const float4* A4 = (const float4*)g_embn;
    const float4* B4 = (const float4*)Win;

    unsigned long long acc[8][4];
    #pragma unroll
    for (int i = 0; i < 8; i++)
        #pragma unroll
        for (int p = 0; p < 4; p++) acc[i][p] = 0ULL;

    for (int kb = 0; kb < EDIM / BKK; kb++) {
        #pragma unroll
        for (int r = 0; r < 2; r++) {                 // A: transpose-load
            int li = tid + r * 256;
            int row = li >> 2, c4 = li & 3;
            float4 v = A4[(mBase + row) * 128 + kb * 4 + c4];
            As[c4 * 4 + 0][row] = v.x; As[c4 * 4 + 1][row] = v.y;
            As[c4 * 4 + 2][row] = v.z; As[c4 * 4 + 3][row] = v.w;
        }
        #pragma unroll
        for (int r = 0; r < 2; r++) {                 // B: direct k-major load
            int li = tid + r * 256;
            int rk = li >> 5, n4 = li & 31;
            float4 v = B4[(kb * BKK + rk) * 128 + blockIdx.x * 32 + n4];
            *(float4*)&Bs[rk][n4 * 4] = v;
        }
        __syncthreads();
        #pragma unroll
        for (int k = 0; k < BKK; k++) {
            float4 a0 = *(const float4*)&As[k][ty * 8];
            float4 a1 = *(const float4*)&As[k][ty * 8 + 4];
            float4 b0 = *(const float4*)&Bs[k][tx * 8];
            float4 b1 = *(const float4*)&Bs[k][tx * 8 + 4];
            float av[8] = {a0.x, a0.y, a0.z, a0.w, a1.x, a1.y, a1.z, a1.w};
            unsigned long long bp[4] = {pk2(b0.x, b0.y), pk2(b0.z, b0.w),
                                        pk2(b1.x, b1.y), pk2(b1.z, b1.w)};
            #pragma unroll
            for (int i = 0; i < 8; i++) {
                unsigned long long ap = pk2(av[i], av[i]);
                #pragma unroll
                for (int p = 0; p < 4; p++) fma2(acc[i][p], ap, bp[p]);
            }
        }
        __syncthreads();
    }
    int nBase = blockIdx.x * BN;
    #pragma unroll
    for (int i = 0; i < 8; i++) {
        int m = mBase + ty * 8 + i;
        #pragma unroll
        for (int p = 0; p < 4; p++) {
            #pragma unroll
            for (int q = 0; q < 2; q++) {
                float v = q ? hi32(acc[i][p]) : lo32(acc[i][p]);
                int col = nBase + tx * 8 + 2 * p + q;
                g_M[m * LATENT + col] = v;
                g_mf16[m * LATENT + col] = __float2half_rn(v);
            }
        }
    }
}

// ---------------- kernel: scores via fp16 mma.sync + top-2/tile -------------
__global__ __launch_bounds__(256) void scores_mma_kernel() {
    extern __shared__ char dyn[];
    __shared__ float t_s[SB_N];

    int tid = threadIdx.x;
    int wid = tid >> 5, lane = tid & 31;
    int wm = wid >> 2, wn = wid & 3;           // 2 x 4 warp grid, warp tile 64x32
    int g = lane >> 2, q = lane & 3;
    int mBase = blockIdx.y * SB_M;
    int nBase = blockIdx.x * SB_N;

    uint32_t sb = smem_u32(dyn);
    if (tid < SB_N) t_s[tid] = g_t[nBase + tid];

    const char* pz = (const char*)g_zf16;
    const char* pm = (const char*)g_mf16;

    float acc[4][4][4];
    #pragma unroll
    for (int t = 0; t < 4; t++)
        #pragma unroll
        for (int n = 0; n < 4; n++)
            #pragma unroll
            for (int e = 0; e < 4; e++) acc[t][n][e] = 0.0f;

    // stage loader: A 128x128B + B 128x128B, 8 cp.async per thread
    auto load_stage = [&](int s, int kb) {
        uint32_t sbase = sb + s * STAGE_BYTES;
        #pragma unroll
        for (int r = 0; r < 4; r++) {
            int li = tid + r * 256;            // 0..1023
            int row = li >> 3, c = li & 7;
            uint32_t dst = sbase + OFF_A + row * ROWB + ((c ^ (row & 7)) * 16);
            CP_ASYNC16(dst, pz + (size_t)(mBase + row) * 1024 + kb * 128 + c * 16);
        }
        #pragma unroll
        for (int r = 0; r < 4; r++) {
            int li = tid + r * 256;
            int row = li >> 3, c = li & 7;
            uint32_t dst = sbase + OFF_B + row * ROWB + ((c ^ (row & 7)) * 16);
            CP_ASYNC16(dst, pm + (size_t)(nBase + row) * 1024 + kb * 128 + c * 16);
        }
        CP_COMMIT();
    };

    load_stage(0, 0);

    for (int kb = 0; kb < NKIT; kb++) {
        int s = kb & 1;
        if (kb + 1 < NKIT) load_stage(s ^ 1, kb + 1);
        if (kb + 1 < NKIT) { CP_WAIT1(); } else { CP_WAIT0(); }
        __syncthreads();

        const char* st = dyn + s * STAGE_BYTES;
        #pragma unroll
        for (int kk = 0; kk < 4; kk++) {
            int ch0 = 2 * kk, ch1 = 2 * kk + 1;
            uint32_t bh[4][2];
            #pragma unroll
            for (int nt = 0; nt < 4; nt++) {
                int n0 = wn * 32 + nt * 8 + g;       // n0 & 7 == g
                const char* bb = st + OFF_B + n0 * ROWB;
                bh[nt][0] = *(const uint32_t*)(bb + ((ch0 ^ g) * 16) + q * 4);
                bh[nt][1] = *(const uint32_t*)(bb + ((ch1 ^ g) * 16) + q * 4);
            }
            #pragma unroll
            for (int t = 0; t < 4; t++) {
                int r0 = wm * 64 + t * 16 + g;       // r0 & 7 == g
                const char* a0 = st + OFF_A + r0 * ROWB;
                const char* a8 = st + OFF_A + (r0 + 8) * ROWB;
                uint32_t ah[4];
                ah[0] = *(const uint32_t*)(a0 + ((ch0 ^ g) * 16) + q * 4);
                ah[1] = *(const uint32_t*)(a8 + ((ch0 ^ g) * 16) + q * 4);
                ah[2] = *(const uint32_t*)(a0 + ((ch1 ^ g) * 16) + q * 4);
                ah[3] = *(const uint32_t*)(a8 + ((ch1 ^ g) * 16) + q * 4);
                #pragma unroll
                for (int nt = 0; nt < 4; nt++) mma_f16(acc[t][nt], ah, bh[nt]);
            }
        }
        __syncthreads();
    }

    // epilogue: bias + per-(lane,row) top-2, quad merge, cross-warp merge
    // reuse dyn smem (all stages dead after final barrier) for the reduction
    unsigned long long (*red)[4][2] = (unsigned long long (*)[4][2])dyn;
    #pragma unroll
    for (int t = 0; t < 4; t++) {
        #pragma unroll
        for (int h = 0; h < 2; h++) {
            float v1 = -3.4e38f, v2 = -3.4e38f;
            int i1 = 0, i2 = 0;
            #pragma unroll
            for (int nt = 0; nt < 4; nt++)
                #pragma unroll
                for (int j = 0; j < 2; j++) {
                    int cloc = wn * 32 + nt * 8 + q * 2 + j;
                    float sval = acc[t][nt][h * 2 + j] + t_s[cloc];
                    int n = nBase + cloc;
                    if (sval > v1) { v2 = v1; i2 = i1; v1 = sval; i1 = n; }
                    else if (sval > v2) { v2 = sval; i2 = n; }
                }
            unsigned long long e1 = ((unsigned long long)float_ord(v1) << 32)
                                  | (unsigned)(NE - 1 - i1);
            unsigned long long e2 = ((unsigned long long)float_ord(v2) << 32)
                                  | (unsigned)(NE - 1 - i2);
            #pragma unroll
            for (int off = 2; off >= 1; off >>= 1) {
                unsigned long long o1 = __shfl_down_sync(0xffffffffu, e1, off);
                unsigned long long o2 = __shfl_down_sync(0xffffffffu, e2, off);
                unsigned long long n1 = umax64(e1, o1);
                unsigned long long n2 = umax64(umin64(e1, o1), umax64(e2, o2));
                e1 = n1; e2 = n2;
            }
            if (q == 0) {
                int row = wm * 64 + t * 16 + h * 8 + g;
                red[row][wn][0] = e1;
                red[row][wn][1] = e2;
            }
        }
    }
    __syncthreads();
    if (tid < SB_M) {
        unsigned long long b1 = 0, b2 = 0;
        #pragma unroll
        for (int w = 0; w < 4; w++) {
            #pragma unroll
            for (int j = 0; j < 2; j++) {
                unsigned long long e = red[tid][w][j];
                if (e > b1) { b2 = b1; b1 = e; }
                else if (e > b2) { b2 = e; }
            }
        }
        size_t base = (size_t)(mBase + tid) * NCAND + blockIdx.x * 2;
        g_cand2[base]     = b1;
        g_cand2[base + 1] = b2;
    }
}

// ---------------- kernel: approx top-8 of 128 candidates + exact rescore ----
__global__ __launch_bounds__(256) void rescore_kernel(const float* __restrict__ z,
                                                      float* __restrict__ idx_out) {
    int row = blockIdx.x * 8 + (threadIdx.x >> 5);
    int lane = threadIdx.x & 31;
    if (row >= MROWS) return;

    float zr[16];
    #pragma unroll
    for (int i = 0; i < 16; i++) zr[i] = z[(size_t)row * LATENT + i * 32 + lane];

    unsigned long long e[4];
    #pragma unroll
    for (int j = 0; j < 4; j++) e[j] = g_cand2[(size_t)row * NCAND + lane + j * 32];

    float bv = -3.4e38f;
    int bn = 0x7fffffff;
    #pragma unroll 1
    for (int it = 0; it < 8; it++) {
        unsigned long long m = e[0];
        #pragma unroll
        for (int j = 1; j < 4; j++) m = umax64(m, e[j]);
        #pragma unroll
        for (int off = 16; off > 0; off >>= 1)
            m = umax64(m, __shfl_xor_sync(0xffffffffu, m, off));
        #pragma unroll
        for (int j = 0; j < 4; j++) if (e[j] == m) e[j] = 0ULL;

        int n = (NE - 1) - (int)(unsigned)(m & 0xFFFFFFFFull);
        const float* Mr = g_M + (size_t)n * LATENT;
        float p = 0.0f;
        #pragma unroll
        for (int i = 0; i < 16; i++) p = fmaf(zr[i], Mr[i * 32 + lane], p);
        #pragma unroll
        for (int off = 16; off > 0; off >>= 1)
            p += __shfl_xor_sync(0xffffffffu, p, off);
        float s = p + g_t[n];
        if (s > bv || (s == bv && n < bn)) { bv = s; bn = n; }
    }
    if (lane == 0) {
        g_idx[row] = bn;
        if (idx_out) idx_out[row] = (float)bn;
    }
}

// ---------------- kernel: Q = emb_n @ W_out^T + b_out  [NT, all 8192 rows] --
__global__ __launch_bounds__(NTHREADS) void gemm_Q_kernel(const float* __restrict__ Wout,
                                                          const float* __restrict__ bout) {
    __shared__ float As[BKK][BM + 4];
    __shared__ float Bs[BKK][BN + 4];
    int tid = threadIdx.x, tx = tid & 15, ty = tid >> 4;
    int mBase = blockIdx.y * BM;
    int nBase = blockIdx.x * BN;
    const float4* A4 = (const float4*)g_embn;
    const float4* B4 = (const float4*)Wout;

    unsigned long long acc[8][4];
    #pragma unroll
    for (int i = 0; i < 8; i++)
        #pragma unroll
        for (int p = 0; p < 4; p++) acc[i][p] = 0ULL;

    for (int kb = 0; kb < EDIM / BKK; kb++) {
        #pragma unroll
        for (int r = 0; r < 2; r++) {                 // A rows (m), k-contig
            int li = tid + r * 256;
            int row = li >> 2, c4 = li & 3;
            float4 v = A4[(size_t)(mBase + row) * 128 + kb * 4 + c4];
            As[c4 * 4 + 0][row] = v.x; As[c4 * 4 + 1][row] = v.y;
            As[c4 * 4 + 2][row] = v.z; As[c4 * 4 + 3][row] = v.w;
        }
        #pragma unroll
        for (int r = 0; r < 2; r++) {                 // B rows (n), k-contig
            int li = tid + r * 256;
            int row = li >> 2, c4 = li & 3;
            float4 v = B4[(size_t)(nBase + row) * 128 + kb * 4 + c4];
            Bs[c4 * 4 + 0][row] = v.x; Bs[c4 * 4 + 1][row] = v.y;
            Bs[c4 * 4 + 2][row] = v.z; Bs[c4 * 4 + 3][row] = v.w;
        }
        __syncthreads();
        #pragma unroll
        for (int k = 0; k < BKK; k++) {
            float4 a0 = *(const float4*)&As[k][ty * 8];
            float4 a1 = *(const float4*)&As[k][ty * 8 + 4];
            float4 b0 = *(const float4*)&Bs[k][tx * 8];
            float4 b1 = *(const float4*)&Bs[k][tx * 8 + 4];
            float av[8] = {a0.x, a0.y, a0.z, a0.w, a1.x, a1.y, a1.z, a1.w};
            unsigned long long bp[4] = {pk2(b0.x, b0.y), pk2(b0.z, b0.w),
                                        pk2(b1.x, b1.y), pk2(b1.z, b1.w)};
            #pragma unroll
            for (int i = 0; i < 8; i++) {
                unsigned long long ap = pk2(av[i], av[i]);
                #pragma unroll
                for (int p = 0; p < 4; p++) fma2(acc[i][p], ap, bp[p]);
            }
        }
        __syncthreads();
    }
    #pragma unroll
    for (int i = 0; i < 8; i++) {
        int m = mBase + ty * 8 + i;
        #pragma unroll
        for (int p = 0; p < 4; p++) {
            int n0 = nBase + tx * 8 + 2 * p;
            g_Q[(size_t)m * LATENT + n0]     = lo32(acc[i][p]) + bout[n0];
            g_Q[(size_t)m * LATENT + n0 + 1] = hi32(acc[i][p]) + bout[n0 + 1];
        }
    }
}

// ---------------- kernel: gather z_q rows from Q ----------------
__global__ void gather_kernel(float4* __restrict__ zq) {
    int m = blockIdx.x;
    int tid = threadIdx.x;              // 128 threads x float4 = 512 floats
    int idx = g_idx[m];
    zq[(size_t)m * 128 + tid] = ((const float4*)g_Q)[(size_t)idx * 128 + tid];
}

// ---------------- host launcher ----------------
extern "C" void kernel_launch(void* const* d_in, const int* in_sizes, int n_in,
                              void* d_out, int out_size) {
    const float* z     = (const float*)d_in[0];
    // d_in[1] = mask (unused by reference)
    const float* W_in  = (const float*)d_in[2];
    const float* b_in  = (const float*)d_in[3];
    const float* W_out = (const float*)d_in[4];
    const float* b_out = (const float*)d_in[5];
    const float* emb   = (const float*)d_in[6];
    float* out = (float*)d_out;

    const long long ZQ = (long long)MROWS * LATENT;  // 8388608
    float* zq_ptr  = nullptr;
    float* idx_ptr = nullptr;
    if ((long long)out_size >= ZQ + MROWS)      { zq_ptr = out; idx_ptr = out + ZQ; }
    else if ((long long)out_size >= ZQ)         { zq_ptr = out; }
    else if (out_size == MROWS)                 { idx_ptr = out; }

    cudaFuncSetAttribute(scores_mma_kernel,
                         cudaFuncAttributeMaxDynamicSharedMemorySize, DYN_SMEM);

    norm_emb_kernel<<<NE, 128>>>((const float4*)emb, (const float4*)b_in);
    conv_z_kernel<<<(MROWS * LATENT / 4) / 256, 256>>>((const float4*)z);
    gemm_M_kernel<<<dim3(LATENT / BN, NE / BM), NTHREADS>>>(W_in);
    gemm_Q_kernel<<<dim3(LATENT / BN, NE / BM), NTHREADS>>>(W_out, b_out);
    scores_mma_kernel<<<dim3(NE / SB_N, MROWS / SB_M), 256, DYN_SMEM>>>();
    rescore_kernel<<<MROWS / 8, 256>>>(z, idx_ptr);
    if (zq_ptr)
        gather_kernel<<<MROWS, 128>>>((float4*)zq_ptr);
}